// round 17
// baseline (speedup 1.0000x reference)
#include <cuda_runtime.h>
#include <cuda_bf16.h>
#include <cstdint>
#include <math.h>

#define BB 32
#define NN 4096
#define DD 256
#define SS 16
#define KK 8
#define HH 128
#define NCHUNK 256
#define NBLK (NN / NCHUNK)      /* 16 chunks per batch */
#define PART (KK * SS + KK)     /* 136 partials per chunk */
#define NPROJ ((BB * NN) / 64)  /* 2048 projection blocks */

// ---------------- device scratch ----------------
__device__ __align__(16) float g_k[BB * NN * SS];
__device__ __align__(16) float g_v[BB * NN * SS];
__device__ __align__(16) float g_partial2[2][BB * NBLK * PART];
__device__ unsigned g_bar[BB * 32];   /* one counter per batch, 128B apart */

// ---------------- helpers ----------------
typedef unsigned long long ull;
__device__ __forceinline__ ull ffma2(ull a, ull b, ull c) {
    ull d;
    asm("fma.rn.f32x2 %0, %1, %2, %3;" : "=l"(d) : "l"(a), "l"(b), "l"(c));
    return d;
}
__device__ __forceinline__ float ull_lo(ull u) {
    return __uint_as_float((unsigned int)(u & 0xffffffffull));
}
__device__ __forceinline__ float ull_hi(ull u) {
    return __uint_as_float((unsigned int)(u >> 32));
}

__device__ __forceinline__ void mma16816(float& c0, float& c1, float& c2,
                                         float& c3, uint32_t a0, uint32_t a1,
                                         uint32_t a2, uint32_t a3, uint32_t b0,
                                         uint32_t b1) {
    asm volatile(
        "mma.sync.aligned.m16n8k16.row.col.f32.bf16.bf16.f32 "
        "{%0,%1,%2,%3}, {%4,%5,%6,%7}, {%8,%9}, {%0,%1,%2,%3};"
        : "+f"(c0), "+f"(c1), "+f"(c2), "+f"(c3)
        : "r"(a0), "r"(a1), "r"(a2), "r"(a3), "r"(b0), "r"(b1));
}
__device__ __forceinline__ void ldm4(uint32_t& r0, uint32_t& r1, uint32_t& r2,
                                     uint32_t& r3, uint32_t addr) {
    asm volatile(
        "ldmatrix.sync.aligned.m8n8.x4.shared.b16 {%0,%1,%2,%3}, [%4];"
        : "=r"(r0), "=r"(r1), "=r"(r2), "=r"(r3) : "r"(addr));
}
__device__ __forceinline__ ull pack_hi_lo(float a, float b, float c, float d,
                                          ull& lo_out) {
    __nv_bfloat162 h0 = __floats2bfloat162_rn(a, b);
    __nv_bfloat162 h1 = __floats2bfloat162_rn(c, d);
    __nv_bfloat162 l0 = __floats2bfloat162_rn(a - __low2float(h0), b - __high2float(h0));
    __nv_bfloat162 l1 = __floats2bfloat162_rn(c - __low2float(h1), d - __high2float(h1));
    lo_out = ((ull)(*(uint32_t*)&l1) << 32) | (*(uint32_t*)&l0);
    return ((ull)(*(uint32_t*)&h1) << 32) | (*(uint32_t*)&h0);
}
__device__ __forceinline__ uint32_t pack2(float a, float b, uint32_t& lo) {
    __nv_bfloat162 h = __floats2bfloat162_rn(a, b);
    __nv_bfloat162 l = __floats2bfloat162_rn(a - __low2float(h), b - __high2float(h));
    lo = *(uint32_t*)&l;
    return *(uint32_t*)&h;
}

// ---------------- Kernel A: two-pass LN + 4x K-split bf16 HMMA --------------
#define RSTR 144
#define A_HI 0
#define A_LO (64 * RSTR)
#define B_HI (2 * 64 * RSTR)
#define B_LO (B_HI + 32 * RSTR)
#define MURS (B_LO + 32 * RSTR)
#define SMEM_LN (MURS + 512)

__global__ void __launch_bounds__(256, 6) ln_proj_tc(
    const float* __restrict__ x, const float* __restrict__ lnw,
    const float* __restrict__ lnb, const float* __restrict__ wk,
    const float* __restrict__ wvm) {
    extern __shared__ char smem[];
    int tid = threadIdx.x, wid = tid >> 5, lane = tid & 31;
    int bx = blockIdx.x;

    // ---- barrier-counter reset block (runs before fused kernel each replay)
    if (bx >= NPROJ) {
        if (tid < BB) g_bar[tid * 32] = 0u;
        return;
    }

    uint32_t sb = (uint32_t)__cvta_generic_to_shared(smem);

    // ---- pass 1: row sums only ----
    {
        float s[8], q[8];
        const float4* xr = (const float4*)(x + ((size_t)bx * 64 + wid * 8) * DD);
#pragma unroll
        for (int rr = 0; rr < 8; rr++) {
            float4 a = xr[rr * 64 + lane];
            float4 c = xr[rr * 64 + lane + 32];
            s[rr] = ((a.x + a.y) + (a.z + a.w)) + ((c.x + c.y) + (c.z + c.w));
            q[rr] = ((a.x * a.x + a.y * a.y) + (a.z * a.z + a.w * a.w)) +
                    ((c.x * c.x + c.y * c.y) + (c.z * c.z + c.w * c.w));
        }
#pragma unroll
        for (int o = 16; o; o >>= 1) {
#pragma unroll
            for (int rr = 0; rr < 8; rr++) {
                s[rr] += __shfl_xor_sync(0xffffffffu, s[rr], o);
                q[rr] += __shfl_xor_sync(0xffffffffu, q[rr], o);
            }
        }
#pragma unroll
        for (int rr = 0; rr < 8; rr++) {
            if (lane == rr) {
                float mu = s[rr] * (1.f / DD);
                float rs = rsqrtf(q[rr] * (1.f / DD) - mu * mu + 1e-5f);
                *(float2*)(smem + MURS + (wid * 8 + rr) * 8) = make_float2(mu, rs);
            }
        }
    }

    int rtile = wid >> 1, chalf = wid & 1;
    float acc[2][4];
#pragma unroll
    for (int t = 0; t < 2; t++)
#pragma unroll
        for (int j = 0; j < 4; j++) acc[t][j] = 0.f;

#pragma unroll 1
    for (int h = 0; h < 4; h++) {
        __syncthreads();

        // ---- stage B K-quarter
        {
            int row = tid >> 3, seg = tid & 7;
            const float* src = ((row < SS) ? (wk + row * DD)
                                           : (wvm + (row - SS) * DD)) +
                               h * 64 + seg * 8;
            char* bh = smem + B_HI + row * RSTR + seg * 16;
            char* bl = smem + B_LO + row * RSTR + seg * 16;
#pragma unroll
            for (int i = 0; i < 2; i++) {
                float4 f = *(const float4*)(src + i * 4);
                ull lo;
                ull hi = pack_hi_lo(f.x, f.y, f.z, f.w, lo);
                *(ull*)(bh + i * 8) = hi;
                *(ull*)(bl + i * 8) = lo;
            }
        }

        // ---- stage A K-quarter: reload x (L2 hit), normalize, split
        {
            const float2* xr2 =
                (const float2*)(x + ((size_t)bx * 64 + wid * 8) * DD + h * 64);
            float2 w2 = ((const float2*)lnw)[h * 32 + lane];
            float2 b2 = ((const float2*)lnb)[h * 32 + lane];
#pragma unroll
            for (int rr = 0; rr < 8; rr++) {
                float2 a = xr2[rr * 128 + lane];
                float2 mr = *(const float2*)(smem + MURS + (wid * 8 + rr) * 8);
                float ox = (a.x - mr.x) * mr.y * w2.x + b2.x;
                float oy = (a.y - mr.x) * mr.y * w2.y + b2.y;
                uint32_t lo;
                uint32_t hi = pack2(ox, oy, lo);
                char* ah = smem + A_HI + (wid * 8 + rr) * RSTR + 4 * lane;
                *(uint32_t*)ah = hi;
                *(uint32_t*)(ah + (A_LO - A_HI)) = lo;
            }
        }
        __syncthreads();

        // ---- MMA
        {
            int tr = lane & 7, sel = lane >> 3;
            uint32_t a_addr = sb + A_HI +
                              (uint32_t)(rtile * 16 + tr + ((sel & 1) << 3)) * RSTR +
                              ((sel >> 1) << 4);
            uint32_t b_addr = sb + B_HI +
                              (uint32_t)(chalf * 16 + tr + ((sel >> 1) << 3)) * RSTR +
                              ((sel & 1) << 4);
#pragma unroll
            for (int ks = 0; ks < 4; ks++) {
                uint32_t ah0, ah1, ah2, ah3, al0, al1, al2, al3;
                uint32_t bh0, bh1, bh2, bh3, bl0, bl1, bl2, bl3;
                ldm4(ah0, ah1, ah2, ah3, a_addr + ks * 32);
                ldm4(al0, al1, al2, al3, a_addr + (A_LO - A_HI) + ks * 32);
                ldm4(bh0, bh1, bh2, bh3, b_addr + ks * 32);
                ldm4(bl0, bl1, bl2, bl3, b_addr + (B_LO - B_HI) + ks * 32);
                mma16816(acc[0][0], acc[0][1], acc[0][2], acc[0][3],
                         ah0, ah1, ah2, ah3, bh0, bh1);
                mma16816(acc[0][0], acc[0][1], acc[0][2], acc[0][3],
                         al0, al1, al2, al3, bh0, bh1);
                mma16816(acc[0][0], acc[0][1], acc[0][2], acc[0][3],
                         ah0, ah1, ah2, ah3, bl0, bl1);
                mma16816(acc[1][0], acc[1][1], acc[1][2], acc[1][3],
                         ah0, ah1, ah2, ah3, bh2, bh3);
                mma16816(acc[1][0], acc[1][1], acc[1][2], acc[1][3],
                         al0, al1, al2, al3, bh2, bh3);
                mma16816(acc[1][0], acc[1][1], acc[1][2], acc[1][3],
                         ah0, ah1, ah2, ah3, bl2, bl3);
            }
        }
    }

    // ---- epilogue
    {
        size_t row0 = (size_t)bx * 64 + rtile * 16 + (lane >> 2);
        int c0 = (lane & 3) * 2;
        float* dst = chalf ? g_v : g_k;
#pragma unroll
        for (int t = 0; t < 2; t++) {
            int col = t * 8 + c0;
            *(float2*)(dst + row0 * SS + col) = make_float2(acc[t][0], acc[t][1]);
            *(float2*)(dst + (row0 + 8) * SS + col) = make_float2(acc[t][2], acc[t][3]);
        }
    }
}

// ---------------- Kernel B: persistent fused attention (3 iters + update) ---
// Grid (NBLK, BB). All 512 blocks co-resident (smem ~44KB, <=64 regs, 4/SM).
// Per-b 16-block barrier via g_bar counter; every block redundantly computes
// the (deterministic) slot update for its own b. Output attn written once,
// already normalized. No update/norm kernels, no global sync.
__global__ void __launch_bounds__(256, 4) attn_fused(
    const float* __restrict__ init_slots, const float* __restrict__ ln_s_w,
    const float* __restrict__ ln_s_b, const float* __restrict__ wq,
    const float* __restrict__ w_ih, const float* __restrict__ w_hh,
    const float* __restrict__ b_ih, const float* __restrict__ b_hh,
    const float* __restrict__ ln_m_w, const float* __restrict__ ln_m_b,
    const float* __restrict__ mlp_w1, const float* __restrict__ mlp_b1,
    const float* __restrict__ mlp_w2, const float* __restrict__ mlp_b2,
    float* __restrict__ out_slots, float* __restrict__ out_attn) {
    __shared__ float sm_q[128];
    __shared__ float sm_slots[128];
    __shared__ ull sm_p2[KK * 257];
    __shared__ float sm_v[NCHUNK * 18];
    __shared__ float2 sm_r[256];
    __shared__ float sm_dp[8 * KK];
    __shared__ float sm_upd[128];
    __shared__ float sm_den[KK];
    __shared__ float sm_y[128];
    __shared__ float sm_h[128];
    __shared__ float sm_h1[KK * HH];
    int tid = threadIdx.x, wid = tid >> 5;
    int nb = blockIdx.x, b = blockIdx.y;
    size_t nrow = (size_t)b * NN + (size_t)nb * NCHUNK + tid;
    unsigned* barp = &g_bar[b * 32];

    // ---- stage k -> regs (kept all 3 iters), v -> smem (kept all 3 iters)
    union { float4 f4[4]; ull u[8]; } kf;
    {
        const float4* kf4 = (const float4*)(g_k + nrow * SS);
#pragma unroll
        for (int j = 0; j < 4; j++) kf.f4[j] = kf4[j];
    }
    {
        const ull* vs =
            (const ull*)(g_v + ((size_t)b * NN + (size_t)nb * NCHUNK) * SS);
#pragma unroll
        for (int i = tid; i < NCHUNK * 8; i += 256) {
            int n = i >> 3, j = i & 7;
            *(ull*)&sm_v[n * 18 + 2 * j] = vs[i];
        }
    }
    if (tid < 128) sm_slots[tid] = init_slots[b * 128 + tid];
    __syncthreads();

#pragma unroll 1
    for (int it = 0; it < 3; it++) {
        int last = (it == 2);
        // ---- q = wq @ LN_s(slots) * scale
        if (tid < 128) {
            int s = tid & 15;
            float v = sm_slots[tid];
            float sum = v, sq = v * v;
#pragma unroll
            for (int o = 8; o; o >>= 1) {
                sum += __shfl_xor_sync(0xffffffffu, sum, o, 16);
                sq += __shfl_xor_sync(0xffffffffu, sq, o, 16);
            }
            float mu = sum * (1.f / SS);
            float rs = rsqrtf(sq * (1.f / SS) - mu * mu + 1e-5f);
            sm_y[tid] = (v - mu) * rs * ln_s_w[s] + ln_s_b[s];
        }
        __syncthreads();
        if (tid < 128) {
            int k = tid >> 4, t = tid & 15;
            float a = 0.f;
#pragma unroll
            for (int ss = 0; ss < SS; ss++) a += sm_y[k * SS + ss] * wq[t * SS + ss];
            sm_q[tid] = a * 0.25f;
        }
        __syncthreads();

        // ---- logits + softmax over slots + denom warp partials
        {
            const float4* q4 = (const float4*)sm_q;
            float lg[KK];
#pragma unroll
            for (int kk = 0; kk < KK; kk++) {
                union { float4 f; ull u[2]; } qa, qb, qc, qd;
                qa.f = q4[kk * 4 + 0];
                qb.f = q4[kk * 4 + 1];
                qc.f = q4[kk * 4 + 2];
                qd.f = q4[kk * 4 + 3];
                ull a0 = ffma2(qa.u[0], kf.u[0], 0ull);
                ull a1 = ffma2(qa.u[1], kf.u[1], 0ull);
                a0 = ffma2(qb.u[0], kf.u[2], a0);
                a1 = ffma2(qb.u[1], kf.u[3], a1);
                a0 = ffma2(qc.u[0], kf.u[4], a0);
                a1 = ffma2(qc.u[1], kf.u[5], a1);
                a0 = ffma2(qd.u[0], kf.u[6], a0);
                a1 = ffma2(qd.u[1], kf.u[7], a1);
                lg[kk] = (ull_lo(a0) + ull_hi(a0)) + (ull_lo(a1) + ull_hi(a1));
            }
            float m = lg[0];
#pragma unroll
            for (int kk = 1; kk < KK; kk++) m = fmaxf(m, lg[kk]);
            float sum = 0.f;
#pragma unroll
            for (int kk = 0; kk < KK; kk++) {
                lg[kk] = __expf(lg[kk] - m);
                sum += lg[kk];
            }
            float inv = 1.f / sum;
#pragma unroll
            for (int kk = 0; kk < KK; kk++) {
                float p = lg[kk] * inv + 1e-8f;
                lg[kk] = p;
                unsigned int pb = __float_as_uint(p);
                sm_p2[kk * 257 + tid] = ((ull)pb << 32) | pb;
            }
#pragma unroll
            for (int o = 16; o; o >>= 1) {
#pragma unroll
                for (int kk = 0; kk < KK; kk++)
                    lg[kk] += __shfl_xor_sync(0xffffffffu, lg[kk], o);
            }
            if ((tid & 31) == 0) {
#pragma unroll
                for (int kk = 0; kk < KK; kk++) sm_dp[wid * KK + kk] = lg[kk];
            }
        }
        __syncthreads();

        // ---- numerator tail: (quarter, k, cpair)
        {
            int quarter = tid >> 6, k = (tid >> 3) & 7, cp = tid & 7;
            const ull* prow = sm_p2 + k * 257;
            ull a0 = 0ull, a1 = 0ull, a2 = 0ull, a3 = 0ull;
            int n0 = quarter * 64;
#pragma unroll 2
            for (int n = n0; n < n0 + 64; n += 4) {
                a0 = ffma2(prow[n], *(const ull*)&sm_v[n * 18 + 2 * cp], a0);
                a1 = ffma2(prow[n + 1], *(const ull*)&sm_v[(n + 1) * 18 + 2 * cp], a1);
                a2 = ffma2(prow[n + 2], *(const ull*)&sm_v[(n + 2) * 18 + 2 * cp], a2);
                a3 = ffma2(prow[n + 3], *(const ull*)&sm_v[(n + 3) * 18 + 2 * cp], a3);
            }
            sm_r[tid] =
                make_float2((ull_lo(a0) + ull_lo(a1)) + (ull_lo(a2) + ull_lo(a3)),
                            (ull_hi(a0) + ull_hi(a1)) + (ull_hi(a2) + ull_hi(a3)));
        }
        __syncthreads();

        // ---- write this block's partials (double-buffered by parity)
        {
            float* gp = g_partial2[it & 1] + ((size_t)(b * NBLK + nb)) * PART;
            if (tid < 64) {
                int k = tid >> 3, cp = tid & 7;
                float2 A = sm_r[tid], B = sm_r[tid + 64];
                float2 C = sm_r[tid + 128], D = sm_r[tid + 192];
                gp[k * SS + 2 * cp] = (A.x + B.x) + (C.x + D.x);
                gp[k * SS + 2 * cp + 1] = (A.y + B.y) + (C.y + D.y);
            } else if (tid < 72) {
                int k = tid - 64;
                float d = 0.f;
#pragma unroll
                for (int w = 0; w < 8; w++) d += sm_dp[w * KK + k];
                gp[128 + k] = d;
            }
        }
        __threadfence();
        __syncthreads();
        if (tid == 0) {
            atomicAdd(barp, 1u);
            unsigned target = 16u * (unsigned)(it + 1);
            unsigned vv;
            do {
                asm volatile("ld.acquire.gpu.u32 %0, [%1];" : "=r"(vv) : "l"(barp));
                if (vv >= target) break;
                __nanosleep(64);
            } while (1);
            __threadfence();
        }
        __syncthreads();

        // ---- reduce all 16 chunks' partials (L2 reads, bypass L1)
        if (tid < PART) {
            const float* base = g_partial2[it & 1] + (size_t)b * NBLK * PART + tid;
            float s0 = 0.f, s1 = 0.f, s2 = 0.f, s3 = 0.f;
#pragma unroll
            for (int j = 0; j < NBLK; j += 4) {
                s0 += __ldcg(base + (size_t)j * PART);
                s1 += __ldcg(base + (size_t)(j + 1) * PART);
                s2 += __ldcg(base + (size_t)(j + 2) * PART);
                s3 += __ldcg(base + (size_t)(j + 3) * PART);
            }
            float s = (s0 + s1) + (s2 + s3);
            if (tid < 128) sm_upd[tid] = s;
            else sm_den[tid - 128] = s;
        }
        __syncthreads();
        if (tid < 128) sm_upd[tid] = sm_upd[tid] / sm_den[tid >> 4];
        __syncthreads();

        // ---- GRU + LN_m (t < 128)
        if (tid < 128) {
            int k = tid >> 4, s = tid & 15;
            float ir = b_ih[s], iz = b_ih[SS + s], inn = b_ih[2 * SS + s];
            float hr = b_hh[s], hz = b_hh[SS + s], hn = b_hh[2 * SS + s];
#pragma unroll
            for (int tt = 0; tt < SS; tt++) {
                float u = sm_upd[k * SS + tt], hp = sm_slots[k * SS + tt];
                ir += w_ih[s * SS + tt] * u;
                iz += w_ih[(SS + s) * SS + tt] * u;
                inn += w_ih[(2 * SS + s) * SS + tt] * u;
                hr += w_hh[s * SS + tt] * hp;
                hz += w_hh[(SS + s) * SS + tt] * hp;
                hn += w_hh[(2 * SS + s) * SS + tt] * hp;
            }
            float r = 1.f / (1.f + __expf(-(ir + hr)));
            float z = 1.f / (1.f + __expf(-(iz + hz)));
            float n = tanhf(inn + r * hn);
            float h = (1.f - z) * n + z * sm_slots[tid];
            sm_h[tid] = h;
            float sum = h, sq = h * h;
#pragma unroll
            for (int o = 8; o; o >>= 1) {
                sum += __shfl_xor_sync(0xffffffffu, sum, o, 16);
                sq += __shfl_xor_sync(0xffffffffu, sq, o, 16);
            }
            float mu = sum * (1.f / SS);
            float rs = rsqrtf(sq * (1.f / SS) - mu * mu + 1e-5f);
            sm_y[tid] = (h - mu) * rs * ln_m_w[s] + ln_m_b[s];
        }
        __syncthreads();

        // ---- MLP1: 1024 units over 256 threads
#pragma unroll
        for (int i = tid; i < KK * HH; i += 256) {
            int k = i >> 7, hh = i & 127;
            float a = mlp_b1[hh];
#pragma unroll
            for (int s = 0; s < SS; s++) a += mlp_w1[hh * SS + s] * sm_y[k * SS + s];
            sm_h1[i] = fmaxf(a, 0.f);
        }
        __syncthreads();

        // ---- MLP2: 128 outputs x 2 threads + residual -> new slots
        {
            int o = tid >> 1, part = tid & 1;
            int k = o >> 4, s = o & 15;
            float a = 0.f;
#pragma unroll 8
            for (int j = 0; j < 64; j++)
                a += mlp_w2[s * HH + part * 64 + j] * sm_h1[k * HH + part * 64 + j];
            a += __shfl_xor_sync(0xffffffffu, a, 1, 2);
            if (part == 0) sm_slots[o] = sm_h[o] + mlp_b2[s] + a;
        }
        __syncthreads();

        // ---- final outputs
        if (last) {
            if (nb == 0 && tid < 128) out_slots[b * 128 + tid] = sm_slots[tid];
#pragma unroll
            for (int kk = 0; kk < KK; kk++) {
                float p = ull_lo(sm_p2[kk * 257 + tid]);
                out_attn[((size_t)(b * KK + kk)) * NN + nb * NCHUNK + tid] =
                    p / sm_den[kk];
            }
        }
    }
}

// ---------------- launch ----------------
extern "C" void kernel_launch(void* const* d_in, const int* in_sizes, int n_in,
                              void* d_out, int out_size) {
    (void)in_sizes; (void)n_in; (void)out_size;
    const float* inputs     = (const float*)d_in[0];
    const float* init_slots = (const float*)d_in[1];
    const float* ln_in_w    = (const float*)d_in[2];
    const float* ln_in_b    = (const float*)d_in[3];
    const float* ln_s_w     = (const float*)d_in[4];
    const float* ln_s_b     = (const float*)d_in[5];
    const float* ln_m_w     = (const float*)d_in[6];
    const float* ln_m_b     = (const float*)d_in[7];
    const float* wq         = (const float*)d_in[8];
    const float* wk         = (const float*)d_in[9];
    const float* wv         = (const float*)d_in[10];
    const float* w_ih       = (const float*)d_in[11];
    const float* w_hh       = (const float*)d_in[12];
    const float* b_ih       = (const float*)d_in[13];
    const float* b_hh       = (const float*)d_in[14];
    const float* mlp_w1     = (const float*)d_in[15];
    const float* mlp_b1     = (const float*)d_in[16];
    const float* mlp_w2     = (const float*)d_in[17];
    const float* mlp_b2     = (const float*)d_in[18];
    float* out = (float*)d_out;
    float* out_slots = out;
    float* out_attn = out + BB * KK * SS;

    cudaFuncSetAttribute(ln_proj_tc, cudaFuncAttributeMaxDynamicSharedMemorySize,
                         SMEM_LN);
    ln_proj_tc<<<NPROJ + 1, 256, SMEM_LN>>>(inputs, ln_in_w, ln_in_b, wk, wv);
    dim3 gf(NBLK, BB);
    attn_fused<<<gf, 256>>>(init_slots, ln_s_w, ln_s_b, wq, w_ih, w_hh, b_ih,
                            b_hh, ln_m_w, ln_m_b, mlp_w1, mlp_b1, mlp_w2,
                            mlp_b2, out_slots, out_attn);
}